// round 1
// baseline (speedup 1.0000x reference)
#include <cuda_runtime.h>

// Problem constants (from reference setup_inputs):
// B=32, S=12, F=128, K=8, H=64, C=64, N=512
#define BB   32
#define SEQ  12
#define FF   128
#define KK   8
#define HH   64
#define CC   64
#define NNN  512

// Scratch (allocation-free rule: __device__ globals)
__device__ float g_WhO[BB * CC];   // per-batch second-layer row (32x64)
__device__ float g_Wfs[CC * CC];   // Wf reduced over n: Wfs[c'][c] = sum_n Wf[c', n*64+c]

// Stage 1: blocks [0,32) compute the per-batch GAT collapse; blocks [32,96)
// reduce one row of Wf each. 256 threads per block.
__global__ void __launch_bounds__(256) gat_stage1(
    const float* __restrict__ x,        // (32,12,128)
    const float* __restrict__ W_heads,  // (8,128,64)
    const float* __restrict__ W_out,    // (512,64)
    const float* __restrict__ Wf)       // (64, 512*64)
{
    __shared__ float s_x[FF];
    __shared__ float s_hcat[KK * HH];   // 512
    __shared__ float s_part[256];

    const int blk = blockIdx.x;
    const int t   = threadIdx.x;

    if (blk < BB) {
        // ---- per-batch branch ----
        // load x[b, 11, :]
        if (t < FF) s_x[t] = x[blk * SEQ * FF + (SEQ - 1) * FF + t];
        __syncthreads();

        // Wh_row[k,h] = sum_f x_f * W_heads[k,f,h]; then elu -> h_cat
        for (int o = t; o < KK * HH; o += 256) {
            const int k = o >> 6;
            const int h = o & 63;
            const float* w = W_heads + (size_t)k * FF * HH + h;
            float acc = 0.f;
            #pragma unroll 8
            for (int f = 0; f < FF; ++f) acc = fmaf(s_x[f], w[f * HH], acc);
            s_hcat[o] = (acc > 0.f) ? acc : (expf(acc) - 1.f);  // elu
        }
        __syncthreads();

        // Wh_o_row[c] = sum_j hcat[j] * W_out[j*64 + c], split j over 4 groups
        const int c = t & 63;
        const int g = t >> 6;         // 0..3, each covers 128 j's
        float acc = 0.f;
        const int j0 = g * 128;
        #pragma unroll 8
        for (int j = j0; j < j0 + 128; ++j)
            acc = fmaf(s_hcat[j], W_out[j * CC + c], acc);
        s_part[t] = acc;
        __syncthreads();
        if (t < CC) {
            g_WhO[blk * CC + t] =
                s_part[t] + s_part[t + 64] + s_part[t + 128] + s_part[t + 192];
        }
    } else {
        // ---- Wf reduction branch: one output row c' per block ----
        const int cp = blk - BB;                       // 0..63
        const float* row = Wf + (size_t)cp * (NNN * CC);
        const int c = t & 63;
        const int g = t >> 6;                          // 4 n-phases
        float acc = 0.f;
        #pragma unroll 8
        for (int j = 0; j < NNN / 4; ++j) {            // n = g + 4*j
            const int n = g + 4 * j;
            acc += row[n * CC + c];
        }
        s_part[t] = acc;
        __syncthreads();
        if (t < CC) {
            g_Wfs[cp * CC + t] =
                s_part[t] + s_part[t + 64] + s_part[t + 128] + s_part[t + 192];
        }
    }
}

// Stage 2: final[b,c'] = bf[c'] + sum_c WhO[b,c] * Wfs[c',c]
__global__ void __launch_bounds__(64) gat_stage2(
    const float* __restrict__ bf,
    float* __restrict__ out)
{
    __shared__ float s_v[CC];
    const int b  = blockIdx.x;
    const int cp = threadIdx.x;
    s_v[cp] = g_WhO[b * CC + cp];
    __syncthreads();
    const float* wrow = g_Wfs + cp * CC;
    float acc = bf[cp];
    #pragma unroll
    for (int c = 0; c < CC; ++c) acc = fmaf(s_v[c], wrow[c], acc);
    out[b * CC + cp] = acc;
}

extern "C" void kernel_launch(void* const* d_in, const int* in_sizes, int n_in,
                              void* d_out, int out_size)
{
    const float* x       = (const float*)d_in[0];  // (32,12,128)
    const float* W_heads = (const float*)d_in[1];  // (8,128,64)
    // d_in[2], d_in[3]: a1_heads / a2_heads — analytically unused (uniform softmax)
    const float* W_out   = (const float*)d_in[4];  // (512,64)
    // d_in[5], d_in[6]: a1_out / a2_out — unused
    const float* Wf      = (const float*)d_in[7];  // (64, 32768)
    const float* bf      = (const float*)d_in[8];  // (64,)
    float* out           = (float*)d_out;          // (32,64)

    gat_stage1<<<BB + CC, 256>>>(x, W_heads, W_out, Wf);
    gat_stage2<<<BB, CC>>>(bf, out);
}